// round 3
// baseline (speedup 1.0000x reference)
#include <cuda_runtime.h>
#include <math.h>

#define BATCH 4
#define HH 128
#define WW 128
#define HW (HH*WW)

// ---- scratch (static device globals; no allocation allowed) ----
__device__ float g_feat[BATCH*130*HW];   // concat input to conv1
__device__ float g_h1[BATCH*64*HW];
__device__ float g_h2[BATCH*64*HW];
__device__ float g_om[BATCH*432*HW];     // [0:288)=final offsets, [288:432)=sigmoid mask

// buffer selector so host code never needs cudaGetSymbolAddress
__device__ __forceinline__ float* bufsel(int i) {
    switch (i) {
        case 0: return g_feat;
        case 1: return g_h1;
        case 2: return g_h2;
        default: return g_om;
    }
}

// =====================================================================
// concat: feat = [x_flow_warped(64) | x_current(64) | flow(2)]
// =====================================================================
__global__ void concat_k(const float* __restrict__ xfw,
                         const float* __restrict__ xc,
                         const float* __restrict__ fl)
{
    int i = blockIdx.x * 256 + threadIdx.x;
    const int total = BATCH * 130 * HW;
    if (i >= total) return;
    int b = i / (130 * HW);
    int r = i - b * 130 * HW;
    int c = r / HW;
    int p = r - c * HW;
    float v;
    if (c < 64)       v = xfw[((size_t)b*64 + c) * HW + p];
    else if (c < 128) v = xc [((size_t)b*64 + (c-64)) * HW + p];
    else              v = fl [((size_t)b*2  + (c-128)) * HW + p];
    g_feat[i] = v;
}

// =====================================================================
// direct 3x3 SAME conv, NCHW.
// tile: 32x32 spatial, 256 threads, each thread 4 pixels x COB couts.
// mode: 1 = bias+lrelu, 2 = DCN epilogue (tanh/flow/sigmoid)
// grid: (W/32, (H/32)*B, Cout/COB)
// =====================================================================
#define TILE 32
#define HALO 34
#define HPAD 36
#define CSTEP 8
#define COB 16

__global__ __launch_bounds__(256)
void conv3x3_k(int in_sel, const float* __restrict__ wt,
               const float* __restrict__ bias, int out_sel,
               int Cin, int Cout, int mode, const float* __restrict__ flow)
{
    __shared__ float s_in[CSTEP][HALO][HPAD];
    __shared__ float s_w[CSTEP][COB][10];

    const float* in  = bufsel(in_sel);
    float*       out = bufsel(out_sel);

    const int tx0 = blockIdx.x * TILE;
    const int ty0 = (blockIdx.y & 3) * TILE;
    const int b   = blockIdx.y >> 2;
    const int oc0 = blockIdx.z * COB;
    const int tid = threadIdx.x;
    const int px = tid & 31;
    const int py = tid >> 5;        // 0..7 ; pixels at rows py, py+8, py+16, py+24

    float acc[4][COB];
#pragma unroll
    for (int p = 0; p < 4; p++)
#pragma unroll
        for (int o = 0; o < COB; o++) acc[p][o] = 0.f;

    const float* inb = in + (size_t)b * Cin * HW;

    for (int c0 = 0; c0 < Cin; c0 += CSTEP) {
        __syncthreads();
        // stage CSTEP input tiles (with zero-pad halo)
        for (int i = tid; i < CSTEP * HALO * HALO; i += 256) {
            int cc = i / (HALO * HALO);
            int rr = (i / HALO) % HALO;
            int cl = i % HALO;
            int gy = ty0 + rr - 1;
            int gx = tx0 + cl - 1;
            int c  = c0 + cc;
            float v = 0.f;
            if (c < Cin && gy >= 0 && gy < HH && gx >= 0 && gx < WW)
                v = inb[(size_t)c * HW + gy * WW + gx];
            s_in[cc][rr][cl] = v;
        }
        // stage weights for this cout block
        for (int i = tid; i < CSTEP * COB * 9; i += 256) {
            int cc = i / (COB * 9);
            int o  = (i / 9) % COB;
            int t  = i % 9;
            int c  = c0 + cc;
            s_w[cc][o][t] = (c < Cin) ? wt[((size_t)(oc0 + o) * Cin + c) * 9 + t] : 0.f;
        }
        __syncthreads();

#pragma unroll
        for (int cc = 0; cc < CSTEP; cc++) {
            float iv[4][9];
#pragma unroll
            for (int p = 0; p < 4; p++) {
                int ry = py + p * 8;
#pragma unroll
                for (int t = 0; t < 9; t++)
                    iv[p][t] = s_in[cc][ry + t / 3][px + t % 3];
            }
#pragma unroll
            for (int o = 0; o < COB; o++) {
#pragma unroll
                for (int t = 0; t < 9; t++) {
                    float wv = s_w[cc][o][t];
#pragma unroll
                    for (int p = 0; p < 4; p++)
                        acc[p][o] = fmaf(iv[p][t], wv, acc[p][o]);
                }
            }
        }
    }

    // epilogue
#pragma unroll
    for (int o = 0; o < COB; o++) {
        int oc = oc0 + o;
        float bv = bias[oc];
#pragma unroll
        for (int p = 0; p < 4; p++) {
            int y = ty0 + py + p * 8;
            int x = tx0 + px;
            float v = acc[p][o] + bv;
            if (mode == 1) {
                v = (v >= 0.f) ? v : 0.1f * v;
            } else {
                if (oc < 288) {
                    // offset channel: 10*tanh + tiled reversed flow
                    // even channel (dy) gets flow ch1, odd (dx) gets flow ch0
                    float fa = flow[((size_t)b * 2 + ((oc & 1) ? 0 : 1)) * HW + y * WW + x];
                    v = 10.f * tanhf(v) + fa;
                } else {
                    v = 1.f / (1.f + expf(-v));
                }
            }
            out[((size_t)b * Cout + oc) * HW + y * WW + x] = v;
        }
    }
}

// =====================================================================
// deformable conv: per pixel, 16 groups x 9 taps bilinear gather of 4
// group-channels, masked, then 576-dim dot per output channel (64).
// grid: B*H*W/256 blocks, 256 threads (1 pixel/thread, all 64 couts)
// =====================================================================
__global__ __launch_bounds__(256)
void deform_k(const float* __restrict__ x,
              const float* __restrict__ wt, const float* __restrict__ bias,
              float* __restrict__ out)
{
    __shared__ __align__(16) float s_w[64 * 9 * 4];   // [o][k][cg], cg contiguous

    const int tid = threadIdx.x;
    const int pix = blockIdx.x * 256 + tid;
    const int b = pix / HW;
    const int p = pix - b * HW;
    const int h = p / WW;
    const int w = p - h * WW;

    float acc[64];
#pragma unroll
    for (int o = 0; o < 64; o++) acc[o] = 0.f;

    const float* omb = g_om + (size_t)b * 432 * HW;

    for (int g = 0; g < 16; g++) {
        __syncthreads();
        // stage weights for this group's 4 channels: w[o][g*4+cg][k]
        for (int i = tid; i < 64 * 9 * 4; i += 256) {
            int o  = i / 36;
            int k  = (i / 4) % 9;
            int cg = i & 3;
            s_w[i] = wt[((size_t)o * 64 + g * 4 + cg) * 9 + k];
        }
        __syncthreads();

        const float* xb = x + ((size_t)b * 64 + g * 4) * HW;

#pragma unroll
        for (int k = 0; k < 9; k++) {
            int ch2 = (g * 9 + k) * 2;
            float dy = omb[(size_t)ch2       * HW + p];
            float dx = omb[(size_t)(ch2 + 1) * HW + p];
            float m  = omb[(size_t)(288 + g * 9 + k) * HW + p];

            float pyf = (float)(h - 1 + k / 3) + dy;
            float pxf = (float)(w - 1 + k % 3) + dx;
            float y0f = floorf(pyf), x0f = floorf(pxf);
            int y0 = (int)y0f, x0 = (int)x0f;
            float wy = pyf - y0f, wx = pxf - x0f;

            float w00 = (1.f - wy) * (1.f - wx);
            float w01 = (1.f - wy) * wx;
            float w10 = wy * (1.f - wx);
            float w11 = wy * wx;

            bool v0 = (y0 >= 0) && (y0 < HH);
            bool v1 = (y0 + 1 >= 0) && (y0 + 1 < HH);
            bool u0 = (x0 >= 0) && (x0 < WW);
            bool u1 = (x0 + 1 >= 0) && (x0 + 1 < WW);
            float f00 = (v0 && u0) ? w00 : 0.f;
            float f01 = (v0 && u1) ? w01 : 0.f;
            float f10 = (v1 && u0) ? w10 : 0.f;
            float f11 = (v1 && u1) ? w11 : 0.f;

            int yc0 = min(max(y0, 0), HH - 1);
            int yc1 = min(max(y0 + 1, 0), HH - 1);
            int xc0 = min(max(x0, 0), WW - 1);
            int xc1 = min(max(x0 + 1, 0), WW - 1);
            int i00 = yc0 * WW + xc0, i01 = yc0 * WW + xc1;
            int i10 = yc1 * WW + xc0, i11 = yc1 * WW + xc1;

            float val[4];
#pragma unroll
            for (int cg = 0; cg < 4; cg++) {
                const float* xc = xb + cg * HW;
                float v = f00 * xc[i00] + f01 * xc[i01]
                        + f10 * xc[i10] + f11 * xc[i11];
                val[cg] = v * m;
            }
#pragma unroll
            for (int o = 0; o < 64; o++) {
                const float4 wv = *reinterpret_cast<const float4*>(&s_w[(o * 9 + k) * 4]);
                acc[o] = fmaf(val[0], wv.x,
                         fmaf(val[1], wv.y,
                         fmaf(val[2], wv.z,
                         fmaf(val[3], wv.w, acc[o]))));
            }
        }
    }

#pragma unroll
    for (int o = 0; o < 64; o++)
        out[((size_t)b * 64 + o) * HW + p] = acc[o] + bias[o];
}

// =====================================================================
extern "C" void kernel_launch(void* const* d_in, const int* in_sizes, int n_in,
                              void* d_out, int out_size)
{
    const float* x    = (const float*)d_in[0];
    const float* xfw  = (const float*)d_in[1];
    const float* xcur = (const float*)d_in[2];
    const float* flow = (const float*)d_in[3];
    const float* w1   = (const float*)d_in[4];
    const float* b1   = (const float*)d_in[5];
    const float* w2   = (const float*)d_in[6];
    const float* b2   = (const float*)d_in[7];
    const float* w3   = (const float*)d_in[8];
    const float* b3   = (const float*)d_in[9];
    const float* w4   = (const float*)d_in[10];
    const float* b4   = (const float*)d_in[11];
    const float* wdc  = (const float*)d_in[12];
    const float* bdc  = (const float*)d_in[13];

    const int totalFeat = BATCH * 130 * HW;
    concat_k<<<(totalFeat + 255) / 256, 256>>>(xfw, xcur, flow);

    dim3 grid1(WW / TILE, (HH / TILE) * BATCH, 64 / COB);
    conv3x3_k<<<grid1, 256>>>(0, w1, b1, 1, 130, 64, 1, nullptr);   // feat -> h1
    conv3x3_k<<<grid1, 256>>>(1, w2, b2, 2,  64, 64, 1, nullptr);   // h1 -> h2
    conv3x3_k<<<grid1, 256>>>(2, w3, b3, 1,  64, 64, 1, nullptr);   // h2 -> h1 (reuse)
    dim3 grid4(WW / TILE, (HH / TILE) * BATCH, 432 / COB);
    conv3x3_k<<<grid4, 256>>>(1, w4, b4, 3,  64, 432, 2, flow);     // h1 -> om

    deform_k<<<(BATCH * HW) / 256, 256>>>(x, wdc, bdc, (float*)d_out);
}